// round 14
// baseline (speedup 1.0000x reference)
#include <cuda_runtime.h>
#include <cuda_fp16.h>
#include <cstdint>

#define B_ 4
#define N_ 4096
#define C_ 256
#define H_ 4
#define D_ 64
#define M_ (B_*N_)   // 16384

// flash tiling
#define QT 256
#define KT 128            // KV rows per iteration
#define NIT (N_/KT)       // 32
#define FSTR 36           // h2-word stride: Q/K rows (64 halves + pad) = 144 B
#define VSTR 68           // h2-word stride: V^T rows (128 halves + pad) = 272 B
#define PSTR 36           // gemm smem stride (144 B rows)

// ---------------- scratch (device globals; no allocation allowed) ----------------
__device__ __half g_qf [B_*H_*N_*D_];
__device__ __half g_ksb[B_*H_*N_*D_];
__device__ __half g_vsb[B_*H_*N_*D_];   // V dir0, TRANSPOSED [b,h,d,n]
__device__ __half g_qsb[B_*H_*N_*D_];
__device__ __half g_kfb[B_*H_*N_*D_];
__device__ __half g_vfb[B_*H_*N_*D_];   // V dir1, TRANSPOSED
__device__ __half g_cat[(size_t)M_ * 2 * C_];
__device__ __half g_xf [(size_t)M_ * C_];
__device__ __half g_xs [(size_t)M_ * C_];
__device__ __half g_wh [6 * C_ * C_];
__device__ __half g_wph[C_ * 2 * C_];

#define QSC (0.125f * 1.44269504088896340736f)

// ---------------- helpers ----------------
__device__ __forceinline__ uint32_t packh2(float lo, float hi) {
    uint32_t r;
    asm("cvt.rn.f16x2.f32 %0, %2, %1;" : "=r"(r) : "f"(lo), "f"(hi));
    return r;
}

__device__ __forceinline__ uint32_t ex2h2(uint32_t x) {
    uint32_t r;
    asm("ex2.approx.f16x2 %0, %1;" : "=r"(r) : "r"(x));
    return r;
}

__device__ __forceinline__ uint32_t hadd2(uint32_t x, uint32_t y) {
    uint32_t r;
    asm("add.f16x2 %0, %1, %2;" : "=r"(r) : "r"(x), "r"(y));
    return r;
}

// fp32-accumulator mma (PV, GEMMs)
__device__ __forceinline__ void mma16(float* d, const uint32_t* a, uint32_t b0, uint32_t b1) {
    asm volatile(
        "mma.sync.aligned.m16n8k16.row.col.f32.f16.f16.f32 "
        "{%0,%1,%2,%3}, {%4,%5,%6,%7}, {%8,%9}, {%0,%1,%2,%3};\n"
        : "+f"(d[0]), "+f"(d[1]), "+f"(d[2]), "+f"(d[3])
        : "r"(a[0]), "r"(a[1]), "r"(a[2]), "r"(a[3]), "r"(b0), "r"(b1));
}

// fp16-accumulator mma (QK: output packed f16x2 in A-frag layout)
__device__ __forceinline__ void mma16h(uint32_t* d, const uint32_t* a, uint32_t b0, uint32_t b1) {
    asm volatile(
        "mma.sync.aligned.m16n8k16.row.col.f16.f16.f16.f16 "
        "{%0,%1}, {%2,%3,%4,%5}, {%6,%7}, {%0,%1};\n"
        : "+r"(d[0]), "+r"(d[1])
        : "r"(a[0]), "r"(a[1]), "r"(a[2]), "r"(a[3]), "r"(b0), "r"(b1));
}

// ldmatrix x4: 4 fragment registers in one shared-memory instruction
__device__ __forceinline__ void ldsm4(uint32_t& r0, uint32_t& r1, uint32_t& r2, uint32_t& r3,
                                      uint32_t addr) {
    asm volatile("ldmatrix.sync.aligned.m8n8.x4.shared.b16 {%0,%1,%2,%3}, [%4];"
        : "=r"(r0), "=r"(r1), "=r"(r2), "=r"(r3) : "r"(addr));
}

__device__ __forceinline__ uint32_t smem_u32(const void* p) {
    uint32_t a;
    asm("{ .reg .u64 t; cvta.to.shared.u64 t, %1; cvt.u32.u64 %0, t; }" : "=r"(a) : "l"(p));
    return a;
}

#define CP_ASYNC16(dst_u32, src_ptr) \
    asm volatile("cp.async.cg.shared.global [%0], [%1], 16;" :: "r"(dst_u32), "l"(src_ptr))
#define CP_COMMIT() asm volatile("cp.async.commit_group;" ::: "memory")
#define CP_WAIT1()  asm volatile("cp.async.wait_group 1;"  ::: "memory")

// ---------------- fp32 -> fp16 conversion pass ----------------
struct ConvArgs {
    const float* src[9];
    __half*      dst[9];
    int          n[9];
};

__global__ void __launch_bounds__(256) conv_fp16(ConvArgs ca) {
    const int a = blockIdx.y;
    const int n8 = ca.n[a] >> 3;
    const float4* s = (const float4*)ca.src[a];
    uint4* d = (uint4*)ca.dst[a];
    for (int i = blockIdx.x * blockDim.x + threadIdx.x; i < n8; i += gridDim.x * blockDim.x) {
        float4 v0 = s[2*i], v1 = s[2*i + 1];
        d[i] = make_uint4(packh2(v0.x, v0.y), packh2(v0.z, v0.w),
                          packh2(v1.x, v1.y), packh2(v1.z, v1.w));
    }
}

// ---- LDSM lane offsets (bytes) shared by both GEMMs (stride PSTR*4 = 144 B) ----
#define ALANE(lane) ((uint32_t)(((lane) & 15) * (PSTR*4) + (((lane) >> 4) & 1) * 16))
#define BLANE(lane) ((uint32_t)(((((lane) >> 4) * 8) + ((lane) & 7)) * (PSTR*4) + (((lane) >> 3) & 1) * 16))

// ---------------- projection GEMM: all-fp16, cp.async pipeline + LDSM, 2 CTAs/SM ----------------
struct Proj2Args {
    const __half* X[6];
    const __half* W[6];
    const float*  Bv[6];
    __half*       Y[6];
};

__global__ void __launch_bounds__(256, 2) proj_gemm(Proj2Args pa) {
    extern __shared__ uint32_t dsm[];
    const uint32_t xb0 = smem_u32(dsm);
    const uint32_t xb1 = xb0 + 128*PSTR*4;
    const uint32_t wb0 = xb0 + 2*128*PSTR*4;
    const uint32_t wb1 = xb0 + 3*128*PSTR*4;
    uint32_t* Xb[2] = { dsm,               dsm + 128*PSTR };
    uint32_t* Wb[2] = { dsm + 2*128*PSTR,  dsm + 3*128*PSTR };

    const int p = blockIdx.z;
    const int mode = p % 3;
    const __half* __restrict__ X = pa.X[p];
    const __half* __restrict__ W = pa.W[p];
    const float*  __restrict__ bias = pa.Bv[p];
    __half* __restrict__ Y = pa.Y[p];

    const int tid  = threadIdx.x;
    const int w    = tid >> 5;
    const int lane = tid & 31;
    const int g    = lane >> 2;
    const int q    = lane & 3;
    const int m0 = blockIdx.y * 128;
    const int n0 = blockIdx.x * 128;

    const int lr = tid >> 3;
    const int lc = tid & 7;

    const uint32_t alane = ALANE(lane) + (uint32_t)(16*w) * (PSTR*4);
    const uint32_t blane = BLANE(lane);

#define PROJ_LOAD(buf, k0) do { \
    _Pragma("unroll") \
    for (int i_ = 0; i_ < 4; i_++) { \
        int r_ = lr + i_*32; \
        CP_ASYNC16(smem_u32(&Xb[buf][r_*PSTR + lc*4]), X + (size_t)(m0 + r_)*C_ + (k0) + lc*8); \
        CP_ASYNC16(smem_u32(&Wb[buf][r_*PSTR + lc*4]), W + (size_t)(n0 + r_)*C_ + (k0) + lc*8); \
    } \
} while (0)

    PROJ_LOAD(0, 0);  CP_COMMIT();
    PROJ_LOAD(1, 64); CP_COMMIT();

    float acc[16][4];
#pragma unroll
    for (int i = 0; i < 16; i++) { acc[i][0]=0.f; acc[i][1]=0.f; acc[i][2]=0.f; acc[i][3]=0.f; }

#pragma unroll
    for (int k = 0; k < 4; k++) {
        CP_WAIT1();
        __syncthreads();
        const uint32_t xA = ((k & 1) ? xb1 : xb0) + alane;
        const uint32_t wB = ((k & 1) ? wb1 : wb0) + blane;
#pragma unroll
        for (int kd = 0; kd < 4; kd++) {
            uint32_t a[4];
            ldsm4(a[0], a[1], a[2], a[3], xA + kd * 32);
#pragma unroll
            for (int np = 0; np < 8; np++) {
                uint32_t b0a, b1a, b0b, b1b;
                ldsm4(b0a, b1a, b0b, b1b, wB + (uint32_t)(np * 16 * (PSTR*4) + kd * 32));
                mma16(acc[2*np    ], a, b0a, b1a);
                mma16(acc[2*np + 1], a, b0b, b1b);
            }
        }
        __syncthreads();
        if (k + 2 < 4) PROJ_LOAD(k & 1, (k + 2) * 64);
        CP_COMMIT();
    }
#undef PROJ_LOAD

    const int row0 = m0 + 16*w + g;
    const int b = row0 >> 12;
    const int n0r = row0 & (N_ - 1);
#pragma unroll
    for (int nt = 0; nt < 16; nt++) {
        const int col = n0 + 8*nt + 2*q;
        const int h = col >> 6, d = col & 63;
        float v00 = acc[nt][0] + __ldg(bias + col);
        float v01 = acc[nt][1] + __ldg(bias + col + 1);
        float v10 = acc[nt][2] + __ldg(bias + col);
        float v11 = acc[nt][3] + __ldg(bias + col + 1);
        if (mode == 0) { v00 *= QSC; v01 *= QSC; v10 *= QSC; v11 *= QSC; }
        if (mode != 2) {
            size_t i0 = ((size_t)(b*H_ + h)*N_ + n0r    )*D_ + d;
            size_t i1 = ((size_t)(b*H_ + h)*N_ + n0r + 8)*D_ + d;
            *(uint32_t*)&Y[i0] = packh2(v00, v01);
            *(uint32_t*)&Y[i1] = packh2(v10, v11);
        } else {
            size_t base = ((size_t)(b*H_ + h)*D_ + d)*N_ + n0r;
            Y[base         ] = __float2half_rn(v00);
            Y[base + N_    ] = __float2half_rn(v01);
            Y[base + 8     ] = __float2half_rn(v10);
            Y[base + N_ + 8] = __float2half_rn(v11);
        }
    }
}

// ---------------- final GEMM: cat fp16 x Wp fp16, cp.async + LDSM, 2 CTAs/SM ----------------
__global__ void __launch_bounds__(256, 2) final_gemm(
    const __half* __restrict__ X, const __half* __restrict__ W,
    const float* __restrict__ bias, float* __restrict__ Y)
{
    extern __shared__ uint32_t dsm[];
    const uint32_t xb0 = smem_u32(dsm);
    const uint32_t xb1 = xb0 + 128*PSTR*4;
    const uint32_t wb0 = xb0 + 2*128*PSTR*4;
    const uint32_t wb1 = xb0 + 3*128*PSTR*4;
    uint32_t* Xb[2] = { dsm,               dsm + 128*PSTR };
    uint32_t* Wb[2] = { dsm + 2*128*PSTR,  dsm + 3*128*PSTR };

    const int tid  = threadIdx.x;
    const int w    = tid >> 5;
    const int lane = tid & 31;
    const int g    = lane >> 2;
    const int q    = lane & 3;
    const int m0 = blockIdx.y * 128;
    const int n0 = blockIdx.x * 128;

    const int lr = tid >> 3;
    const int lc = tid & 7;

    const uint32_t alane = ALANE(lane) + (uint32_t)(16*w) * (PSTR*4);
    const uint32_t blane = BLANE(lane);

#define FIN_LOAD(buf, k0) do { \
    _Pragma("unroll") \
    for (int i_ = 0; i_ < 4; i_++) { \
        int r_ = lr + i_*32; \
        CP_ASYNC16(smem_u32(&Xb[buf][r_*PSTR + lc*4]), X + (size_t)(m0 + r_)*(2*C_) + (k0) + lc*8); \
        CP_ASYNC16(smem_u32(&Wb[buf][r_*PSTR + lc*4]), W + (size_t)(n0 + r_)*(2*C_) + (k0) + lc*8); \
    } \
} while (0)

    FIN_LOAD(0, 0);  CP_COMMIT();
    FIN_LOAD(1, 64); CP_COMMIT();

    float acc[16][4];
#pragma unroll
    for (int i = 0; i < 16; i++) { acc[i][0]=0.f; acc[i][1]=0.f; acc[i][2]=0.f; acc[i][3]=0.f; }

#pragma unroll
    for (int k = 0; k < 8; k++) {
        CP_WAIT1();
        __syncthreads();
        const uint32_t xA = ((k & 1) ? xb1 : xb0) + alane;
        const uint32_t wB = ((k & 1) ? wb1 : wb0) + blane;
#pragma unroll
        for (int kd = 0; kd < 4; kd++) {
            uint32_t a[4];
            ldsm4(a[0], a[1], a[2], a[3], xA + kd * 32);
#pragma unroll
            for (int np = 0; np < 8; np++) {
                uint32_t b0a, b1a, b0b, b1b;
                ldsm4(b0a, b1a, b0b, b1b, wB + (uint32_t)(np * 16 * (PSTR*4) + kd * 32));
                mma16(acc[2*np    ], a, b0a, b1a);
                mma16(acc[2*np + 1], a, b0b, b1b);
            }
        }
        __syncthreads();
        if (k + 2 < 8) FIN_LOAD(k & 1, (k + 2) * 64);
        CP_COMMIT();
    }
#undef FIN_LOAD

    const int row0 = m0 + 16*w + g;
    const int row1 = row0 + 8;
#pragma unroll
    for (int nt = 0; nt < 16; nt++) {
        int col = n0 + 8*nt + 2*q;
        float b0v = __ldg(bias + col), b1v = __ldg(bias + col + 1);
        *(float2*)&Y[(size_t)row0*C_ + col] = make_float2(acc[nt][0] + b0v, acc[nt][1] + b1v);
        *(float2*)&Y[(size_t)row1*C_ + col] = make_float2(acc[nt][2] + b0v, acc[nt][3] + b1v);
    }
}

// ---------------- flash attention v10: HADD2 row sums (no ones-mma) ----------------
__global__ void __launch_bounds__(256, 2) flash_fp16(
    const __half* __restrict__ qf,  const __half* __restrict__ ksb, const __half* __restrict__ vsb,
    const __half* __restrict__ qsb, const __half* __restrict__ kfb, const __half* __restrict__ vfb,
    __half* __restrict__ cat)
{
    extern __shared__ uint32_t sm[];
    uint32_t* Qs  = sm;                        // 256*36
    uint32_t* Kb0 = sm + QT*FSTR;              // 128*36
    uint32_t* Kb1 = Kb0 + KT*FSTR;             // 128*36
    uint32_t* Vb0 = Kb1 + KT*FSTR;             // 64*68
    uint32_t* Vb1 = Vb0 + D_*VSTR;             // 64*68

    const int dir = blockIdx.z;
    const int bh  = blockIdx.y;
    const int q0  = blockIdx.x * QT;

    const __half* Qg  = (dir ? qsb : qf ) + (size_t)bh * N_ * D_;
    const __half* Kg  = (dir ? kfb : ksb) + (size_t)bh * N_ * D_;
    const __half* Vtg = (dir ? vfb : vsb) + (size_t)bh * N_ * D_;   // [d][n]

    const int tid  = threadIdx.x;
    const int w    = tid >> 5;
    const int lane = tid & 31;
    const int g    = lane >> 2;
    const int q    = lane & 3;

    const int kr = tid >> 3, kc = tid & 7;       // K: 128 rows x 8 chunks
    const int vr = tid >> 4, vc = tid & 15;      // V^T: 64 rows x 16 chunks

    const uint32_t klane = (uint32_t)(((lane >> 4) * 8 + (lane & 7)) * (FSTR*4) + ((lane >> 3) & 1) * 16);
    const uint32_t vlane = (uint32_t)((lane >> 4) * 8 * (VSTR*4) + (lane & 7) * (VSTR*4) + ((lane >> 3) & 1) * 16);

    const uint32_t kb0 = smem_u32(Kb0), kb1 = smem_u32(Kb1);
    const uint32_t vb0 = smem_u32(Vb0), vb1 = smem_u32(Vb1);

#define KV_LOAD(Kd, Vd, kv0) do { \
    _Pragma("unroll") \
    for (int i_ = 0; i_ < 4; i_++) { \
        int r_ = kr + i_*32; \
        CP_ASYNC16(smem_u32(&(Kd)[r_*FSTR + kc*4]), Kg + (size_t)((kv0) + r_)*D_ + kc*8); \
        int d_ = vr + i_*16; \
        CP_ASYNC16(smem_u32(&(Vd)[d_*VSTR + vc*4]), Vtg + (size_t)d_*N_ + (kv0) + vc*8); \
    } \
} while (0)

    // ---- prologue ----
#pragma unroll
    for (int i = 0; i < 8; i++) {
        int idx = tid + i * 256;
        int r = idx >> 3, c = idx & 7;
        CP_ASYNC16(smem_u32(&Qs[r*FSTR + c*4]), Qg + (size_t)(q0 + r)*D_ + c*8);
    }
    KV_LOAD(Kb0, Vb0, 0);
    CP_COMMIT();
    KV_LOAD(Kb1, Vb1, KT);
    CP_COMMIT();
    CP_WAIT1();
    __syncthreads();

    uint32_t qa[2][4][4];
#pragma unroll
    for (int mt = 0; mt < 2; mt++) {
        const int row = 32*w + 16*mt + g;
#pragma unroll
        for (int kd = 0; kd < 4; kd++) {
            qa[mt][kd][0] = Qs[(row    )*FSTR + 8*kd + q    ];
            qa[mt][kd][1] = Qs[(row + 8)*FSTR + 8*kd + q    ];
            qa[mt][kd][2] = Qs[(row    )*FSTR + 8*kd + q + 4];
            qa[mt][kd][3] = Qs[(row + 8)*FSTR + 8*kd + q + 4];
        }
    }

    float o[2][8][4];
#pragma unroll
    for (int mt = 0; mt < 2; mt++)
#pragma unroll
        for (int nt = 0; nt < 8; nt++) { o[mt][nt][0]=0.f; o[mt][nt][1]=0.f; o[mt][nt][2]=0.f; o[mt][nt][3]=0.f; }
    float osum[2][2];   // [mt][0]=row g partial, [mt][1]=row g+8 partial (per-thread, quad-reduced at end)
#pragma unroll
    for (int mt = 0; mt < 2; mt++) { osum[mt][0]=0.f; osum[mt][1]=0.f; }

#pragma unroll 1
    for (int it = 0; it < NIT; it++) {
        const uint32_t kB = ((it & 1) ? kb1 : kb0) + klane;
        const uint32_t vB = ((it & 1) ? vb1 : vb0) + vlane;

        uint32_t hs[2][2] = {{0u, 0u}, {0u, 0u}};   // fp16x2 per-iter row-sum accumulators

#pragma unroll
        for (int ks = 0; ks < 8; ks++) {
            uint32_t sh[2][2][2];
#pragma unroll
            for (int mt = 0; mt < 2; mt++)
#pragma unroll
                for (int ntl = 0; ntl < 2; ntl++) { sh[mt][ntl][0] = 0u; sh[mt][ntl][1] = 0u; }
#pragma unroll
            for (int kd = 0; kd < 4; kd++) {
                uint32_t b0a, b1a, b0b, b1b;
                ldsm4(b0a, b1a, b0b, b1b, kB + (uint32_t)(ks * 16 * (FSTR*4) + kd * 32));
                mma16h(sh[0][0], qa[0][kd], b0a, b1a);
                mma16h(sh[1][0], qa[1][kd], b0a, b1a);
                mma16h(sh[0][1], qa[0][kd], b0b, b1b);
                mma16h(sh[1][1], qa[1][kd], b0b, b1b);
            }
            uint32_t a[2][4];
#pragma unroll
            for (int mt = 0; mt < 2; mt++) {
                a[mt][0] = ex2h2(sh[mt][0][0]);
                a[mt][1] = ex2h2(sh[mt][0][1]);
                a[mt][2] = ex2h2(sh[mt][1][0]);
                a[mt][3] = ex2h2(sh[mt][1][1]);
                // row sums on the ALU pipe (replaces ones-mma on the tensor pipe)
                hs[mt][0] = hadd2(hs[mt][0], hadd2(a[mt][0], a[mt][2]));   // row g
                hs[mt][1] = hadd2(hs[mt][1], hadd2(a[mt][1], a[mt][3]));   // row g+8
            }
#pragma unroll
            for (int j = 0; j < 4; j++) {
                uint32_t v0a, v1a, v0b, v1b;
                ldsm4(v0a, v1a, v0b, v1b, vB + (uint32_t)(j * 16 * (VSTR*4) + ks * 32));
                mma16(o[0][2*j    ], a[0], v0a, v1a);
                mma16(o[1][2*j    ], a[1], v0a, v1a);
                mma16(o[0][2*j + 1], a[0], v0b, v1b);
                mma16(o[1][2*j + 1], a[1], v0b, v1b);
            }
        }

        // fold per-iter fp16 partials into fp32 (bounds fp16 accumulation error)
#pragma unroll
        for (int mt = 0; mt < 2; mt++) {
            float2 f0 = __half22float2(*(__half2*)&hs[mt][0]);
            float2 f1 = __half22float2(*(__half2*)&hs[mt][1]);
            osum[mt][0] += f0.x + f0.y;
            osum[mt][1] += f1.x + f1.y;
        }

        __syncthreads();
        if (it + 2 < NIT) {
            uint32_t* Kd = (it & 1) ? Kb1 : Kb0;
            uint32_t* Vd = (it & 1) ? Vb1 : Vb0;
            KV_LOAD(Kd, Vd, (it + 2) * KT);
        }
        CP_COMMIT();
        CP_WAIT1();
        __syncthreads();
    }
#undef KV_LOAD

    // quad-reduce row sums (threads q=0..3 hold disjoint kv columns of the same row)
#pragma unroll
    for (int mt = 0; mt < 2; mt++) {
#pragma unroll
        for (int hf = 0; hf < 2; hf++) {
            float v = osum[mt][hf];
            v += __shfl_xor_sync(0xffffffffu, v, 1);
            v += __shfl_xor_sync(0xffffffffu, v, 2);
            osum[mt][hf] = 1.0f / v;
        }
    }

    const int b = bh >> 2;
    const int h = bh & 3;
#pragma unroll
    for (int mt = 0; mt < 2; mt++) {
        const float i0 = osum[mt][0];
        const float i1 = osum[mt][1];
        const int row0 = q0 + 32*w + 16*mt + g;
        __half* dst0 = cat + ((size_t)b * N_ + row0) * (2*C_) + dir*C_ + h*D_ + 2*q;
        __half* dst1 = dst0 + 8 * (2*C_);
#pragma unroll
        for (int nt = 0; nt < 8; nt++) {
            *(uint32_t*)(dst0 + 8*nt) = packh2(o[mt][nt][0]*i0, o[mt][nt][1]*i0);
            *(uint32_t*)(dst1 + 8*nt) = packh2(o[mt][nt][2]*i1, o[mt][nt][3]*i1);
        }
    }
}

// ---------------- LayerNorm over last dim (in-place on d_out) ----------------
__global__ void __launch_bounds__(256) ln_kernel(
    float* __restrict__ out, const float* __restrict__ gamma, const float* __restrict__ beta)
{
    const int row  = blockIdx.x * 8 + (threadIdx.x >> 5);
    const int lane = threadIdx.x & 31;
    float* p = out + (size_t)row * C_ + lane * 8;
    float4 v0 = *(float4*)p;
    float4 v1 = *(float4*)(p + 4);
    float sum = v0.x+v0.y+v0.z+v0.w + v1.x+v1.y+v1.z+v1.w;
    float sq  = v0.x*v0.x+v0.y*v0.y+v0.z*v0.z+v0.w*v0.w
              + v1.x*v1.x+v1.y*v1.y+v1.z*v1.z+v1.w*v1.w;
#pragma unroll
    for (int off = 16; off >= 1; off >>= 1) {
        sum += __shfl_xor_sync(0xffffffffu, sum, off);
        sq  += __shfl_xor_sync(0xffffffffu, sq,  off);
    }
    const float mean = sum * (1.0f / C_);
    const float var  = sq  * (1.0f / C_) - mean * mean;
    const float inv  = rsqrtf(var + 1e-5f);
    const float4 gg0 = *(const float4*)(gamma + lane*8);
    const float4 gg1 = *(const float4*)(gamma + lane*8 + 4);
    const float4 bb0 = *(const float4*)(beta  + lane*8);
    const float4 bb1 = *(const float4*)(beta  + lane*8 + 4);
    v0.x = (v0.x - mean)*inv*gg0.x + bb0.x;
    v0.y = (v0.y - mean)*inv*gg0.y + bb0.y;
    v0.z = (v0.z - mean)*inv*gg0.z + bb0.z;
    v0.w = (v0.w - mean)*inv*gg0.w + bb0.w;
    v1.x = (v1.x - mean)*inv*gg1.x + bb1.x;
    v1.y = (v1.y - mean)*inv*gg1.y + bb1.y;
    v1.z = (v1.z - mean)*inv*gg1.z + bb1.z;
    v1.w = (v1.w - mean)*inv*gg1.w + bb1.w;
    *(float4*)p       = v0;
    *(float4*)(p + 4) = v1;
}

// ---------------- launch ----------------
extern "C" void kernel_launch(void* const* d_in, const int* in_sizes, int n_in,
                              void* d_out, int out_size) {
    (void)in_sizes; (void)n_in; (void)out_size;
    const float* f_freq = (const float*)d_in[0];
    const float* f_spat = (const float*)d_in[1];
    const float* Wqf = (const float*)d_in[2];  const float* bqf = (const float*)d_in[3];
    const float* Wks = (const float*)d_in[4];  const float* bks = (const float*)d_in[5];
    const float* Wvs = (const float*)d_in[6];  const float* bvs = (const float*)d_in[7];
    const float* Wqs = (const float*)d_in[8];  const float* bqs = (const float*)d_in[9];
    const float* Wkf = (const float*)d_in[10]; const float* bkf = (const float*)d_in[11];
    const float* Wvf = (const float*)d_in[12]; const float* bvf = (const float*)d_in[13];
    const float* Wp  = (const float*)d_in[14]; const float* bp  = (const float*)d_in[15];
    const float* gamma = (const float*)d_in[16];
    const float* beta  = (const float*)d_in[17];
    float* out = (float*)d_out;

    __half *qf, *ksb, *vsb, *qsb, *kfb, *vfb, *cat, *xf, *xs, *wh, *wph;
    cudaGetSymbolAddress((void**)&qf,  g_qf);
    cudaGetSymbolAddress((void**)&ksb, g_ksb);
    cudaGetSymbolAddress((void**)&vsb, g_vsb);
    cudaGetSymbolAddress((void**)&qsb, g_qsb);
    cudaGetSymbolAddress((void**)&kfb, g_kfb);
    cudaGetSymbolAddress((void**)&vfb, g_vfb);
    cudaGetSymbolAddress((void**)&cat, g_cat);
    cudaGetSymbolAddress((void**)&xf,  g_xf);
    cudaGetSymbolAddress((void**)&xs,  g_xs);
    cudaGetSymbolAddress((void**)&wh,  g_wh);
    cudaGetSymbolAddress((void**)&wph, g_wph);

    ConvArgs ca;
    ca.src[0] = f_freq; ca.dst[0] = xf;              ca.n[0] = M_ * C_;
    ca.src[1] = f_spat; ca.dst[1] = xs;              ca.n[1] = M_ * C_;
    ca.src[2] = Wqf;    ca.dst[2] = wh + 0*C_*C_;    ca.n[2] = C_ * C_;
    ca.src[3] = Wks;    ca.dst[3] = wh + 1*C_*C_;    ca.n[3] = C_ * C_;
    ca.src[4] = Wvs;    ca.dst[4] = wh + 2*C_*C_;    ca.n[4] = C_ * C_;
    ca.src[5] = Wqs;    ca.dst[5] = wh + 3*C_*C_;    ca.n[5] = C_ * C_;
    ca.src[6] = Wkf;    ca.dst[6] = wh + 4*C_*C_;    ca.n[6] = C_ * C_;
    ca.src[7] = Wvf;    ca.dst[7] = wh + 5*C_*C_;    ca.n[7] = C_ * C_;
    ca.src[8] = Wp;     ca.dst[8] = wph;             ca.n[8] = C_ * 2 * C_;
    conv_fp16<<<dim3(128, 9), 256>>>(ca);

    Proj2Args pa;
    pa.X[0]=xf; pa.W[0]=wh+0*C_*C_; pa.Bv[0]=bqf; pa.Y[0]=qf;
    pa.X[1]=xs; pa.W[1]=wh+1*C_*C_; pa.Bv[1]=bks; pa.Y[1]=ksb;
    pa.X[2]=xs; pa.W[2]=wh+2*C_*C_; pa.Bv[2]=bvs; pa.Y[2]=vsb;
    pa.X[3]=xs; pa.W[3]=wh+3*C_*C_; pa.Bv[3]=bqs; pa.Y[3]=qsb;
    pa.X[4]=xf; pa.W[4]=wh+4*C_*C_; pa.Bv[4]=bkf; pa.Y[4]=kfb;
    pa.X[5]=xf; pa.W[5]=wh+5*C_*C_; pa.Bv[5]=bvf; pa.Y[5]=vfb;

    const int gsm = 4 * 128 * PSTR * 4;
    cudaFuncSetAttribute(proj_gemm, cudaFuncAttributeMaxDynamicSharedMemorySize, gsm);
    proj_gemm<<<dim3(2, 128, 6), 256, gsm>>>(pa);

    const int fsm = (QT*FSTR + 2*KT*FSTR + 2*D_*VSTR) * 4;   // 108,544 B
    cudaFuncSetAttribute(flash_fp16, cudaFuncAttributeMaxDynamicSharedMemorySize, fsm);
    flash_fp16<<<dim3(N_/QT, B_*H_, 2), 256, fsm>>>(qf, ksb, vsb, qsb, kfb, vfb, cat);

    cudaFuncSetAttribute(final_gemm, cudaFuncAttributeMaxDynamicSharedMemorySize, gsm);
    final_gemm<<<dim3(2, 128), 256, gsm>>>(cat, wph, bp, out);

    ln_kernel<<<M_/8, 256>>>(out, gamma, beta);
}

// round 15
// speedup vs baseline: 1.0155x; 1.0155x over previous
#include <cuda_runtime.h>
#include <cuda_fp16.h>
#include <cstdint>

#define B_ 4
#define N_ 4096
#define C_ 256
#define H_ 4
#define D_ 64
#define M_ (B_*N_)   // 16384

// flash tiling
#define QT 256
#define KT 128            // KV rows per iteration
#define NIT (N_/KT)       // 32
#define FSTR 36           // h2-word stride: Q/K rows (64 halves + pad) = 144 B
#define VSTR 68           // h2-word stride: V^T rows (128 halves + pad) = 272 B
#define PSTR 36           // gemm smem stride (144 B rows)
#define ONE2 0x3C003C00u  // fp16x2 {1.0, 1.0}

#define NJOBS 1536        // 6 projections x 128 m-tiles x 2 n-tiles
#define PGRID 304         // persistent proj CTAs (2 per SM x 152 SMs)

// ---------------- scratch (device globals; no allocation allowed) ----------------
__device__ __half g_qf [B_*H_*N_*D_];
__device__ __half g_ksb[B_*H_*N_*D_];
__device__ __half g_vsb[B_*H_*N_*D_];   // V dir0, TRANSPOSED [b,h,d,n]
__device__ __half g_qsb[B_*H_*N_*D_];
__device__ __half g_kfb[B_*H_*N_*D_];
__device__ __half g_vfb[B_*H_*N_*D_];   // V dir1, TRANSPOSED
__device__ __half g_cat[(size_t)M_ * 2 * C_];
__device__ __half g_xf [(size_t)M_ * C_];
__device__ __half g_xs [(size_t)M_ * C_];
__device__ __half g_wh [6 * C_ * C_];
__device__ __half g_wph[C_ * 2 * C_];

#define QSC (0.125f * 1.44269504088896340736f)

// ---------------- helpers ----------------
__device__ __forceinline__ uint32_t packh2(float lo, float hi) {
    uint32_t r;
    asm("cvt.rn.f16x2.f32 %0, %2, %1;" : "=r"(r) : "f"(lo), "f"(hi));
    return r;
}

__device__ __forceinline__ uint32_t ex2h2(uint32_t x) {
    uint32_t r;
    asm("ex2.approx.f16x2 %0, %1;" : "=r"(r) : "r"(x));
    return r;
}

// fp32-accumulator mma (PV, ones-mma, GEMMs)
__device__ __forceinline__ void mma16(float* d, const uint32_t* a, uint32_t b0, uint32_t b1) {
    asm volatile(
        "mma.sync.aligned.m16n8k16.row.col.f32.f16.f16.f32 "
        "{%0,%1,%2,%3}, {%4,%5,%6,%7}, {%8,%9}, {%0,%1,%2,%3};\n"
        : "+f"(d[0]), "+f"(d[1]), "+f"(d[2]), "+f"(d[3])
        : "r"(a[0]), "r"(a[1]), "r"(a[2]), "r"(a[3]), "r"(b0), "r"(b1));
}

// fp16-accumulator mma (QK: output packed f16x2 in A-frag layout)
__device__ __forceinline__ void mma16h(uint32_t* d, const uint32_t* a, uint32_t b0, uint32_t b1) {
    asm volatile(
        "mma.sync.aligned.m16n8k16.row.col.f16.f16.f16.f16 "
        "{%0,%1}, {%2,%3,%4,%5}, {%6,%7}, {%0,%1};\n"
        : "+r"(d[0]), "+r"(d[1])
        : "r"(a[0]), "r"(a[1]), "r"(a[2]), "r"(a[3]), "r"(b0), "r"(b1));
}

// ldmatrix x4
__device__ __forceinline__ void ldsm4(uint32_t& r0, uint32_t& r1, uint32_t& r2, uint32_t& r3,
                                      uint32_t addr) {
    asm volatile("ldmatrix.sync.aligned.m8n8.x4.shared.b16 {%0,%1,%2,%3}, [%4];"
        : "=r"(r0), "=r"(r1), "=r"(r2), "=r"(r3) : "r"(addr));
}

__device__ __forceinline__ uint32_t smem_u32(const void* p) {
    uint32_t a;
    asm("{ .reg .u64 t; cvta.to.shared.u64 t, %1; cvt.u32.u64 %0, t; }" : "=r"(a) : "l"(p));
    return a;
}

#define CP_ASYNC16(dst_u32, src_ptr) \
    asm volatile("cp.async.cg.shared.global [%0], [%1], 16;" :: "r"(dst_u32), "l"(src_ptr))
#define CP_COMMIT() asm volatile("cp.async.commit_group;" ::: "memory")
#define CP_WAIT1()  asm volatile("cp.async.wait_group 1;"  ::: "memory")

// ---------------- fp32 -> fp16 conversion pass ----------------
struct ConvArgs {
    const float* src[9];
    __half*      dst[9];
    int          n[9];
};

__global__ void __launch_bounds__(256) conv_fp16(ConvArgs ca) {
    const int a = blockIdx.y;
    const int n8 = ca.n[a] >> 3;
    const float4* s = (const float4*)ca.src[a];
    uint4* d = (uint4*)ca.dst[a];
    for (int i = blockIdx.x * blockDim.x + threadIdx.x; i < n8; i += gridDim.x * blockDim.x) {
        float4 v0 = s[2*i], v1 = s[2*i + 1];
        d[i] = make_uint4(packh2(v0.x, v0.y), packh2(v0.z, v0.w),
                          packh2(v1.x, v1.y), packh2(v1.z, v1.w));
    }
}

// ---- LDSM lane offsets (bytes) for GEMMs (stride PSTR*4 = 144 B) ----
#define ALANE(lane) ((uint32_t)(((lane) & 15) * (PSTR*4) + (((lane) >> 4) & 1) * 16))
#define BLANE(lane) ((uint32_t)(((((lane) >> 4) * 8) + ((lane) & 7)) * (PSTR*4) + (((lane) >> 3) & 1) * 16))

// ---------------- persistent projection GEMM ----------------
struct Proj2Args {
    const __half* X[6];
    const __half* W[6];
    const float*  Bv[6];
    __half*       Y[6];
};

// job decode: p = job>>8, my = (job&255)>>1, nx = job&1
__device__ __forceinline__ void proj_load_chunk(
    const Proj2Args& pa, int job, int k,
    uint32_t xdst, uint32_t wdst, int lr, int lc)
{
    const int p  = job >> 8;
    const int m0 = ((job & 255) >> 1) * 128;
    const int n0 = (job & 1) * 128;
    const __half* X = pa.X[p];
    const __half* W = pa.W[p];
    const int k0 = k * 64;
#pragma unroll
    for (int i = 0; i < 4; i++) {
        int r = lr + i * 32;
        CP_ASYNC16(xdst + (uint32_t)(r*PSTR*4 + lc*16), X + (size_t)(m0 + r)*C_ + k0 + lc*8);
        CP_ASYNC16(wdst + (uint32_t)(r*PSTR*4 + lc*16), W + (size_t)(n0 + r)*C_ + k0 + lc*8);
    }
}

__global__ void __launch_bounds__(256, 2) proj_gemm(Proj2Args pa) {
    extern __shared__ uint32_t dsm[];
    const uint32_t base = smem_u32(dsm);
    const uint32_t xb[2] = { base,                base + 128*PSTR*4 };
    const uint32_t wb[2] = { base + 2*128*PSTR*4, base + 3*128*PSTR*4 };

    const int tid  = threadIdx.x;
    const int w    = tid >> 5;
    const int lane = tid & 31;
    const int g    = lane >> 2;
    const int q    = lane & 3;
    const int lr = tid >> 3;
    const int lc = tid & 7;

    const uint32_t alane = ALANE(lane) + (uint32_t)(16*w) * (PSTR*4);
    const uint32_t blane = BLANE(lane);

    int job = blockIdx.x;
    if (job < NJOBS) proj_load_chunk(pa, job, 0, xb[0], wb[0], lr, lc);
    CP_COMMIT();
    if (job < NJOBS) proj_load_chunk(pa, job, 1, xb[1], wb[1], lr, lc);
    CP_COMMIT();

    int cc = 0;
#pragma unroll 1
    for (; job < NJOBS; job += PGRID) {
        const int nj = job + PGRID;
        float acc[16][4];
#pragma unroll
        for (int i = 0; i < 16; i++) { acc[i][0]=0.f; acc[i][1]=0.f; acc[i][2]=0.f; acc[i][3]=0.f; }

#pragma unroll
        for (int k = 0; k < 4; k++) {
            CP_WAIT1();
            __syncthreads();
            const int pb = cc & 1;
            const uint32_t xA = xb[pb] + alane;
            const uint32_t wB = wb[pb] + blane;
#pragma unroll
            for (int kd = 0; kd < 4; kd++) {
                uint32_t a[4];
                ldsm4(a[0], a[1], a[2], a[3], xA + kd * 32);
#pragma unroll
                for (int np = 0; np < 8; np++) {
                    uint32_t b0a, b1a, b0b, b1b;
                    ldsm4(b0a, b1a, b0b, b1b, wB + (uint32_t)(np * 16 * (PSTR*4) + kd * 32));
                    mma16(acc[2*np    ], a, b0a, b1a);
                    mma16(acc[2*np + 1], a, b0b, b1b);
                }
            }
            __syncthreads();
            if (k < 2) {
                proj_load_chunk(pa, job, k + 2, xb[pb], wb[pb], lr, lc);
            } else if (nj < NJOBS) {
                proj_load_chunk(pa, nj, k - 2, xb[pb], wb[pb], lr, lc);
            }
            CP_COMMIT();
            cc++;
        }

        // ---- epilogue for this job ----
        const int p  = job >> 8;
        const int mode = p % 3;
        const int m0 = ((job & 255) >> 1) * 128;
        const int n0 = (job & 1) * 128;
        const float* __restrict__ bias = pa.Bv[p];
        __half* __restrict__ Y = pa.Y[p];
        const int row0 = m0 + 16*w + g;
        const int b = row0 >> 12;
        const int n0r = row0 & (N_ - 1);
#pragma unroll
        for (int nt = 0; nt < 16; nt++) {
            const int col = n0 + 8*nt + 2*q;
            const int h = col >> 6, d = col & 63;
            float v00 = acc[nt][0] + __ldg(bias + col);
            float v01 = acc[nt][1] + __ldg(bias + col + 1);
            float v10 = acc[nt][2] + __ldg(bias + col);
            float v11 = acc[nt][3] + __ldg(bias + col + 1);
            if (mode == 0) { v00 *= QSC; v01 *= QSC; v10 *= QSC; v11 *= QSC; }
            if (mode != 2) {
                size_t i0 = ((size_t)(b*H_ + h)*N_ + n0r    )*D_ + d;
                size_t i1 = ((size_t)(b*H_ + h)*N_ + n0r + 8)*D_ + d;
                *(uint32_t*)&Y[i0] = packh2(v00, v01);
                *(uint32_t*)&Y[i1] = packh2(v10, v11);
            } else {
                size_t basev = ((size_t)(b*H_ + h)*D_ + d)*N_ + n0r;
                Y[basev         ] = __float2half_rn(v00);
                Y[basev + N_    ] = __float2half_rn(v01);
                Y[basev + 8     ] = __float2half_rn(v10);
                Y[basev + N_ + 8] = __float2half_rn(v11);
            }
        }
    }
}

// ---------------- final GEMM: cat fp16 x Wp fp16, cp.async + LDSM, 2 CTAs/SM (r13) ----------------
__global__ void __launch_bounds__(256, 2) final_gemm(
    const __half* __restrict__ X, const __half* __restrict__ W,
    const float* __restrict__ bias, float* __restrict__ Y)
{
    extern __shared__ uint32_t dsm[];
    const uint32_t xb0 = smem_u32(dsm);
    const uint32_t xb1 = xb0 + 128*PSTR*4;
    const uint32_t wb0 = xb0 + 2*128*PSTR*4;
    const uint32_t wb1 = xb0 + 3*128*PSTR*4;
    uint32_t* Xb[2] = { dsm,               dsm + 128*PSTR };
    uint32_t* Wb[2] = { dsm + 2*128*PSTR,  dsm + 3*128*PSTR };

    const int tid  = threadIdx.x;
    const int w    = tid >> 5;
    const int lane = tid & 31;
    const int g    = lane >> 2;
    const int q    = lane & 3;
    const int m0 = blockIdx.y * 128;
    const int n0 = blockIdx.x * 128;

    const int lr = tid >> 3;
    const int lc = tid & 7;

    const uint32_t alane = ALANE(lane) + (uint32_t)(16*w) * (PSTR*4);
    const uint32_t blane = BLANE(lane);

#define FIN_LOAD(buf, k0) do { \
    _Pragma("unroll") \
    for (int i_ = 0; i_ < 4; i_++) { \
        int r_ = lr + i_*32; \
        CP_ASYNC16(smem_u32(&Xb[buf][r_*PSTR + lc*4]), X + (size_t)(m0 + r_)*(2*C_) + (k0) + lc*8); \
        CP_ASYNC16(smem_u32(&Wb[buf][r_*PSTR + lc*4]), W + (size_t)(n0 + r_)*(2*C_) + (k0) + lc*8); \
    } \
} while (0)

    FIN_LOAD(0, 0);  CP_COMMIT();
    FIN_LOAD(1, 64); CP_COMMIT();

    float acc[16][4];
#pragma unroll
    for (int i = 0; i < 16; i++) { acc[i][0]=0.f; acc[i][1]=0.f; acc[i][2]=0.f; acc[i][3]=0.f; }

#pragma unroll
    for (int k = 0; k < 8; k++) {
        CP_WAIT1();
        __syncthreads();
        const uint32_t xA = ((k & 1) ? xb1 : xb0) + alane;
        const uint32_t wB = ((k & 1) ? wb1 : wb0) + blane;
#pragma unroll
        for (int kd = 0; kd < 4; kd++) {
            uint32_t a[4];
            ldsm4(a[0], a[1], a[2], a[3], xA + kd * 32);
#pragma unroll
            for (int np = 0; np < 8; np++) {
                uint32_t b0a, b1a, b0b, b1b;
                ldsm4(b0a, b1a, b0b, b1b, wB + (uint32_t)(np * 16 * (PSTR*4) + kd * 32));
                mma16(acc[2*np    ], a, b0a, b1a);
                mma16(acc[2*np + 1], a, b0b, b1b);
            }
        }
        __syncthreads();
        if (k + 2 < 8) FIN_LOAD(k & 1, (k + 2) * 64);
        CP_COMMIT();
    }
#undef FIN_LOAD

    const int row0 = m0 + 16*w + g;
    const int row1 = row0 + 8;
#pragma unroll
    for (int nt = 0; nt < 16; nt++) {
        int col = n0 + 8*nt + 2*q;
        float b0v = __ldg(bias + col), b1v = __ldg(bias + col + 1);
        *(float2*)&Y[(size_t)row0*C_ + col] = make_float2(acc[nt][0] + b0v, acc[nt][1] + b1v);
        *(float2*)&Y[(size_t)row1*C_ + col] = make_float2(acc[nt][2] + b0v, acc[nt][3] + b1v);
    }
}

// ---------------- flash attention (r13 validated): LDSM + fp16-acc QK + ones-mma ----------------
__global__ void __launch_bounds__(256, 2) flash_fp16(
    const __half* __restrict__ qf,  const __half* __restrict__ ksb, const __half* __restrict__ vsb,
    const __half* __restrict__ qsb, const __half* __restrict__ kfb, const __half* __restrict__ vfb,
    __half* __restrict__ cat)
{
    extern __shared__ uint32_t sm[];
    uint32_t* Qs  = sm;                        // 256*36
    uint32_t* Kb0 = sm + QT*FSTR;              // 128*36
    uint32_t* Kb1 = Kb0 + KT*FSTR;             // 128*36
    uint32_t* Vb0 = Kb1 + KT*FSTR;             // 64*68
    uint32_t* Vb1 = Vb0 + D_*VSTR;             // 64*68

    const int dir = blockIdx.z;
    const int bh  = blockIdx.y;
    const int q0  = blockIdx.x * QT;

    const __half* Qg  = (dir ? qsb : qf ) + (size_t)bh * N_ * D_;
    const __half* Kg  = (dir ? kfb : ksb) + (size_t)bh * N_ * D_;
    const __half* Vtg = (dir ? vfb : vsb) + (size_t)bh * N_ * D_;   // [d][n]

    const int tid  = threadIdx.x;
    const int w    = tid >> 5;
    const int lane = tid & 31;
    const int g    = lane >> 2;
    const int q    = lane & 3;

    const int kr = tid >> 3, kc = tid & 7;       // K: 128 rows x 8 chunks
    const int vr = tid >> 4, vc = tid & 15;      // V^T: 64 rows x 16 chunks

    const uint32_t klane = (uint32_t)(((lane >> 4) * 8 + (lane & 7)) * (FSTR*4) + ((lane >> 3) & 1) * 16);
    const uint32_t vlane = (uint32_t)((lane >> 4) * 8 * (VSTR*4) + (lane & 7) * (VSTR*4) + ((lane >> 3) & 1) * 16);

    const uint32_t kb0 = smem_u32(Kb0), kb1 = smem_u32(Kb1);
    const uint32_t vb0 = smem_u32(Vb0), vb1 = smem_u32(Vb1);

#define KV_LOAD(Kd, Vd, kv0) do { \
    _Pragma("unroll") \
    for (int i_ = 0; i_ < 4; i_++) { \
        int r_ = kr + i_*32; \
        CP_ASYNC16(smem_u32(&(Kd)[r_*FSTR + kc*4]), Kg + (size_t)((kv0) + r_)*D_ + kc*8); \
        int d_ = vr + i_*16; \
        CP_ASYNC16(smem_u32(&(Vd)[d_*VSTR + vc*4]), Vtg + (size_t)d_*N_ + (kv0) + vc*8); \
    } \
} while (0)

    // ---- prologue ----
#pragma unroll
    for (int i = 0; i < 8; i++) {
        int idx = tid + i * 256;
        int r = idx >> 3, c = idx & 7;
        CP_ASYNC16(smem_u32(&Qs[r*FSTR + c*4]), Qg + (size_t)(q0 + r)*D_ + c*8);
    }
    KV_LOAD(Kb0, Vb0, 0);
    CP_COMMIT();
    KV_LOAD(Kb1, Vb1, KT);
    CP_COMMIT();
    CP_WAIT1();
    __syncthreads();

    uint32_t qa[2][4][4];
#pragma unroll
    for (int mt = 0; mt < 2; mt++) {
        const int row = 32*w + 16*mt + g;
#pragma unroll
        for (int kd = 0; kd < 4; kd++) {
            qa[mt][kd][0] = Qs[(row    )*FSTR + 8*kd + q    ];
            qa[mt][kd][1] = Qs[(row + 8)*FSTR + 8*kd + q    ];
            qa[mt][kd][2] = Qs[(row    )*FSTR + 8*kd + q + 4];
            qa[mt][kd][3] = Qs[(row + 8)*FSTR + 8*kd + q + 4];
        }
    }

    float o[2][8][4];
#pragma unroll
    for (int mt = 0; mt < 2; mt++)
#pragma unroll
        for (int nt = 0; nt < 8; nt++) { o[mt][nt][0]=0.f; o[mt][nt][1]=0.f; o[mt][nt][2]=0.f; o[mt][nt][3]=0.f; }
    float osum[2][4];
#pragma unroll
    for (int mt = 0; mt < 2; mt++) { osum[mt][0]=0.f; osum[mt][1]=0.f; osum[mt][2]=0.f; osum[mt][3]=0.f; }

#pragma unroll 1
    for (int it = 0; it < NIT; it++) {
        const uint32_t kB = ((it & 1) ? kb1 : kb0) + klane;
        const uint32_t vB = ((it & 1) ? vb1 : vb0) + vlane;

#pragma unroll
        for (int ks = 0; ks < 8; ks++) {
            uint32_t sh[2][2][2];
#pragma unroll
            for (int mt = 0; mt < 2; mt++)
#pragma unroll
                for (int ntl = 0; ntl < 2; ntl++) { sh[mt][ntl][0] = 0u; sh[mt][ntl][1] = 0u; }
#pragma unroll
            for (int kd = 0; kd < 4; kd++) {
                uint32_t b0a, b1a, b0b, b1b;
                ldsm4(b0a, b1a, b0b, b1b, kB + (uint32_t)(ks * 16 * (FSTR*4) + kd * 32));
                mma16h(sh[0][0], qa[0][kd], b0a, b1a);
                mma16h(sh[1][0], qa[1][kd], b0a, b1a);
                mma16h(sh[0][1], qa[0][kd], b0b, b1b);
                mma16h(sh[1][1], qa[1][kd], b0b, b1b);
            }
            uint32_t a[2][4];
#pragma unroll
            for (int mt = 0; mt < 2; mt++) {
                a[mt][0] = ex2h2(sh[mt][0][0]);
                a[mt][1] = ex2h2(sh[mt][0][1]);
                a[mt][2] = ex2h2(sh[mt][1][0]);
                a[mt][3] = ex2h2(sh[mt][1][1]);
                mma16(osum[mt], a[mt], ONE2, ONE2);
            }
#pragma unroll
            for (int j = 0; j < 4; j++) {
                uint32_t v0a, v1a, v0b, v1b;
                ldsm4(v0a, v1a, v0b, v1b, vB + (uint32_t)(j * 16 * (VSTR*4) + ks * 32));
                mma16(o[0][2*j    ], a[0], v0a, v1a);
                mma16(o[1][2*j    ], a[1], v0a, v1a);
                mma16(o[0][2*j + 1], a[0], v0b, v1b);
                mma16(o[1][2*j + 1], a[1], v0b, v1b);
            }
        }

        __syncthreads();
        if (it + 2 < NIT) {
            uint32_t* Kd = (it & 1) ? Kb1 : Kb0;
            uint32_t* Vd = (it & 1) ? Vb1 : Vb0;
            KV_LOAD(Kd, Vd, (it + 2) * KT);
        }
        CP_COMMIT();
        CP_WAIT1();
        __syncthreads();
    }
#undef KV_LOAD

    const int b = bh >> 2;
    const int h = bh & 3;
#pragma unroll
    for (int mt = 0; mt < 2; mt++) {
        const float i0 = 1.0f / osum[mt][0];
        const float i1 = 1.0f / osum[mt][2];
        const int row0 = q0 + 32*w + 16*mt + g;
        __half* dst0 = cat + ((size_t)b * N_ + row0) * (2*C_) + dir*C_ + h*D_ + 2*q;
        __half* dst1 = dst0 + 8 * (2*C_);
#pragma unroll
        for (int nt = 0; nt < 8; nt++) {
            *(uint32_t*)(dst0 + 8*nt) = packh2(o[mt][nt][0]*i0, o[mt][nt][1]*i0);
            *(uint32_t*)(dst1 + 8*nt) = packh2(o[mt][nt][2]*i1, o[mt][nt][3]*i1);
        }
    }
}

// ---------------- LayerNorm over last dim (in-place on d_out) ----------------
__global__ void __launch_bounds__(256) ln_kernel(
    float* __restrict__ out, const float* __restrict__ gamma, const float* __restrict__ beta)
{
    const int row  = blockIdx.x * 8 + (threadIdx.x >> 5);
    const int lane = threadIdx.x & 31;
    float* p = out + (size_t)row * C_ + lane * 8;
    float4 v0 = *(float4*)p;
    float4 v1 = *(float4*)(p + 4);
    float sum = v0.x+v0.y+v0.z+v0.w + v1.x+v1.y+v1.z+v1.w;
    float sq  = v0.x*v0.x+v0.y*v0.y+v0.z*v0.z+v0.w*v0.w
              + v1.x*v1.x+v1.y*v1.y+v1.z*v1.z+v1.w*v1.w;
#pragma unroll
    for (int off = 16; off >= 1; off >>= 1) {
        sum += __shfl_xor_sync(0xffffffffu, sum, off);
        sq  += __shfl_xor_sync(0xffffffffu, sq,  off);
    }
    const float mean = sum * (1.0f / C_);
    const float var  = sq  * (1.0f / C_) - mean * mean;
    const float inv  = rsqrtf(var + 1e-5f);
    const float4 gg0 = *(const float4*)(gamma + lane*8);
    const float4 gg1 = *(const float4*)(gamma + lane*8 + 4);
    const float4 bb0 = *(const float4*)(beta  + lane*8);
    const float4 bb1 = *(const float4*)(beta  + lane*8 + 4);
    v0.x = (v0.x - mean)*inv*gg0.x + bb0.x;
    v0.y = (v0.y - mean)*inv*gg0.y + bb0.y;
    v0.z = (v0.z - mean)*inv*gg0.z + bb0.z;
    v0.w = (v0.w - mean)*inv*gg0.w + bb0.w;
    v1.x = (v1.x - mean)*inv*gg1.x + bb1.x;
    v1.y = (v1.y - mean)*inv*gg1.y + bb1.y;
    v1.z = (v1.z - mean)*inv*gg1.z + bb1.z;
    v1.w = (v1.w - mean)*inv*gg1.w + bb1.w;
    *(float4*)p       = v0;
    *(float4*)(p + 4) = v1;
}

// ---------------- launch ----------------
extern "C" void kernel_launch(void* const* d_in, const int* in_sizes, int n_in,
                              void* d_out, int out_size) {
    (void)in_sizes; (void)n_in; (void)out_size;
    const float* f_freq = (const float*)d_in[0];
    const float* f_spat = (const float*)d_in[1];
    const float* Wqf = (const float*)d_in[2];  const float* bqf = (const float*)d_in[3];
    const float* Wks = (const float*)d_in[4];  const float* bks = (const float*)d_in[5];
    const float* Wvs = (const float*)d_in[6];  const float* bvs = (const float*)d_in[7];
    const float* Wqs = (const float*)d_in[8];  const float* bqs = (const float*)d_in[9];
    const float* Wkf = (const float*)d_in[10]; const float* bkf = (const float*)d_in[11];
    const float* Wvf = (const float*)d_in[12]; const float* bvf = (const float*)d_in[13];
    const float* Wp  = (const float*)d_in[14]; const float* bp  = (const float*)d_in[15];
    const float* gamma = (const float*)d_in[16];
    const float* beta  = (const float*)d_in[17];
    float* out = (float*)d_out;

    __half *qf, *ksb, *vsb, *qsb, *kfb, *vfb, *cat, *xf, *xs, *wh, *wph;
    cudaGetSymbolAddress((void**)&qf,  g_qf);
    cudaGetSymbolAddress((void**)&ksb, g_ksb);
    cudaGetSymbolAddress((void**)&vsb, g_vsb);
    cudaGetSymbolAddress((void**)&qsb, g_qsb);
    cudaGetSymbolAddress((void**)&kfb, g_kfb);
    cudaGetSymbolAddress((void**)&vfb, g_vfb);
    cudaGetSymbolAddress((void**)&cat, g_cat);
    cudaGetSymbolAddress((void**)&xf,  g_xf);
    cudaGetSymbolAddress((void**)&xs,  g_xs);
    cudaGetSymbolAddress((void**)&wh,  g_wh);
    cudaGetSymbolAddress((void**)&wph, g_wph);

    ConvArgs ca;
    ca.src[0] = f_freq; ca.dst[0] = xf;              ca.n[0] = M_ * C_;
    ca.src[1] = f_spat; ca.dst[1] = xs;              ca.n[1] = M_ * C_;
    ca.src[2] = Wqf;    ca.dst[2] = wh + 0*C_*C_;    ca.n[2] = C_ * C_;
    ca.src[3] = Wks;    ca.dst[3] = wh + 1*C_*C_;    ca.n[3] = C_ * C_;
    ca.src[4] = Wvs;    ca.dst[4] = wh + 2*C_*C_;    ca.n[4] = C_ * C_;
    ca.src[5] = Wqs;    ca.dst[5] = wh + 3*C_*C_;    ca.n[5] = C_ * C_;
    ca.src[6] = Wkf;    ca.dst[6] = wh + 4*C_*C_;    ca.n[6] = C_ * C_;
    ca.src[7] = Wvf;    ca.dst[7] = wh + 5*C_*C_;    ca.n[7] = C_ * C_;
    ca.src[8] = Wp;     ca.dst[8] = wph;             ca.n[8] = C_ * 2 * C_;
    conv_fp16<<<dim3(128, 9), 256>>>(ca);

    Proj2Args pa;
    pa.X[0]=xf; pa.W[0]=wh+0*C_*C_; pa.Bv[0]=bqf; pa.Y[0]=qf;
    pa.X[1]=xs; pa.W[1]=wh+1*C_*C_; pa.Bv[1]=bks; pa.Y[1]=ksb;
    pa.X[2]=xs; pa.W[2]=wh+2*C_*C_; pa.Bv[2]=bvs; pa.Y[2]=vsb;
    pa.X[3]=xs; pa.W[3]=wh+3*C_*C_; pa.Bv[3]=bqs; pa.Y[3]=qsb;
    pa.X[4]=xf; pa.W[4]=wh+4*C_*C_; pa.Bv[4]=bkf; pa.Y[4]=kfb;
    pa.X[5]=xf; pa.W[5]=wh+5*C_*C_; pa.Bv[5]=bvf; pa.Y[5]=vfb;

    const int gsm = 4 * 128 * PSTR * 4;
    cudaFuncSetAttribute(proj_gemm, cudaFuncAttributeMaxDynamicSharedMemorySize, gsm);
    proj_gemm<<<PGRID, 256, gsm>>>(pa);

    const int fsm = (QT*FSTR + 2*KT*FSTR + 2*D_*VSTR) * 4;   // 108,544 B
    cudaFuncSetAttribute(flash_fp16, cudaFuncAttributeMaxDynamicSharedMemorySize, fsm);
    flash_fp16<<<dim3(N_/QT, B_*H_, 2), 256, fsm>>>(qf, ksb, vsb, qsb, kfb, vfb, cat);

    cudaFuncSetAttribute(final_gemm, cudaFuncAttributeMaxDynamicSharedMemorySize, gsm);
    final_gemm<<<dim3(2, 128), 256, gsm>>>(cat, wph, bp, out);

    ln_kernel<<<M_/8, 256>>>(out, gamma, beta);
}